// round 16
// baseline (speedup 1.0000x reference)
#include <cuda_runtime.h>
#include <cuda_bf16.h>
#include <math.h>

#define Hdim 1024
#define Ldim 10
#define Vdim 50257
#define NWARP5 16
#define MAXNB5 512
#define ROWS2 7      // k2: rows per block (147*7 >= 1024)

// ---- scratch (no allocations allowed) ----
__device__ __align__(16) float g_x[Hdim];
__device__ __align__(16) float g_hnew[Hdim];
__device__ __align__(16) float g_logits[Vdim];
__device__ float g_pmax[MAXNB5];
__device__ float g_psum[MAXNB5];
__device__ unsigned g_bar_count = 0;
__device__ volatile unsigned g_bar_sense = 0;

__device__ __forceinline__ float warp_sum(float s) {
#pragma unroll
    for (int o = 16; o; o >>= 1) s += __shfl_down_sync(0xffffffffu, s, o);
    return s;
}

__device__ __forceinline__ void lse_merge(float& m, float& s, float m2, float s2) {
    if (m2 > m) { s = s * expf(m - m2) + s2; m = m2; }
    else if (s2 > 0.f) { s += s2 * expf(m2 - m); }
}

__device__ __forceinline__ void l2_prefetch(const void* p) {
    asm volatile("prefetch.global.L2 [%0];" :: "l"(p));
}

__device__ __forceinline__ float dot4(float4 a, float4 b) {
    return a.x * b.x + a.y * b.y + a.z * b.z + a.w * b.w;
}

// K2: 147 blocks x 512. NO gridsync — scores computed in-block from inputs only.
__global__ __launch_bounds__(512) void k2_comb(const float* __restrict__ comb_W,
                                               const float* __restrict__ comb_b,
                                               const int* __restrict__ inp,
                                               const float* __restrict__ emb,
                                               const float* __restrict__ enc,
                                               const float* __restrict__ attn_W,
                                               const float* __restrict__ attn_b,
                                               const float* __restrict__ hidden,
                                               float* __restrict__ out, int out_size) {
    cudaTriggerProgrammaticLaunchCompletion();
    __shared__ __align__(16) float s_xcat[2 * Hdim];
    __shared__ float s_sc[Ldim];
    int tid = threadIdx.x, warp = tid >> 5, lane = tid & 31;
    int r0 = blockIdx.x * ROWS2;

    for (int i = tid; i < ROWS2 * 64; i += 512) {
        int r = r0 + i / 64;
        if (r < Hdim)
            l2_prefetch((const char*)(comb_W + (size_t)r * 2 * Hdim) + (i % 64) * 128);
    }
    int tok = inp[0];
    const float4* erow4 = (const float4*)(emb + (size_t)tok * Hdim);
    const float4* h4 = (const float4*)hidden;

    if (tid < 256)
        ((float4*)s_xcat)[tid] = erow4[tid];

    if (warp < Ldim) {
        const float4* wr = (const float4*)(attn_W + (size_t)warp * 2 * Hdim);
        float s = 0.f;
#pragma unroll
        for (int k = 0; k < 16; k++) {
            int idx = lane + 32 * k;
            float4 x = (idx < 256) ? erow4[idx] : h4[idx - 256];
            s += dot4(__ldg(wr + idx), x);
        }
        s = warp_sum(s);
        if (lane == 0) s_sc[warp] = s + attn_b[warp];
    }
    __syncthreads();

    float wl[Ldim];
    {
        float m = s_sc[0];
#pragma unroll
        for (int l = 1; l < Ldim; l++) m = fmaxf(m, s_sc[l]);
        float ssum = 0.f;
#pragma unroll
        for (int l = 0; l < Ldim; l++) { wl[l] = expf(s_sc[l] - m); ssum += wl[l]; }
        float inv = 1.f / ssum;
#pragma unroll
        for (int l = 0; l < Ldim; l++) wl[l] *= inv;
    }
    if (blockIdx.x == 0 && tid < Ldim && out_size >= Vdim + Hdim + Ldim)
        out[Vdim + Hdim + tid] = wl[tid];

    if (tid < 256) {
        const float4* e4 = (const float4*)enc;
        float4 a = make_float4(0.f, 0.f, 0.f, 0.f);
#pragma unroll
        for (int l = 0; l < Ldim; l++) {
            float4 e = __ldg(e4 + l * 256 + tid);
            a.x += wl[l] * e.x; a.y += wl[l] * e.y;
            a.z += wl[l] * e.z; a.w += wl[l] * e.w;
        }
        ((float4*)s_xcat)[256 + tid] = a;
    }
    __syncthreads();

    if (warp < ROWS2) {
        int r = r0 + warp;
        if (r < Hdim) {
            const float4* wr = (const float4*)(comb_W + (size_t)r * 2 * Hdim);
            const float4* xc = (const float4*)s_xcat;
            float s = 0.f;
#pragma unroll
            for (int k = 0; k < 16; k++) {
                int idx = lane + 32 * k;
                s += dot4(__ldcs(wr + idx), xc[idx]);
            }
            s = warp_sum(s);
            if (lane == 0) g_x[r] = fmaxf(s + comb_b[r], 0.f);
        }
    }
}

// K3: 1024 blocks x 256 threads, ONE unit each. Pre-sync L2-prefetch of 6 rows.
__global__ __launch_bounds__(256) void k3_gru(const float* __restrict__ hidden,
                                              const float* __restrict__ wih,
                                              const float* __restrict__ whh,
                                              const float* __restrict__ bih,
                                              const float* __restrict__ bhh,
                                              float* __restrict__ out, int out_size) {
    __shared__ float red[6][8];
    int u = blockIdx.x;
    int tid = threadIdx.x, warp = tid >> 5, lane = tid & 31;

    const float4* wir = (const float4*)(wih + (size_t)u * Hdim);
    const float4* wiz = (const float4*)(wih + (size_t)(u + Hdim) * Hdim);
    const float4* win = (const float4*)(wih + (size_t)(u + 2 * Hdim) * Hdim);
    const float4* whr = (const float4*)(whh + (size_t)u * Hdim);
    const float4* whz = (const float4*)(whh + (size_t)(u + Hdim) * Hdim);
    const float4* whn = (const float4*)(whh + (size_t)(u + 2 * Hdim) * Hdim);

    for (int i = tid; i < 192; i += 256) {
        int row6 = i / 32, line = i % 32;
        const float* base;
        if (row6 < 3) base = wih + (size_t)(u + row6 * Hdim) * Hdim;
        else          base = whh + (size_t)(u + (row6 - 3) * Hdim) * Hdim;
        l2_prefetch((const char*)base + line * 128);
    }
    float4 hv = ((const float4*)hidden)[tid];

    cudaTriggerProgrammaticLaunchCompletion();
    cudaGridDependencySynchronize();

    float4 xv = ((const float4*)g_x)[tid];
    float s0 = dot4(__ldcs(wir + tid), xv);
    float s1 = dot4(__ldcs(wiz + tid), xv);
    float s2 = dot4(__ldcs(win + tid), xv);
    float s3 = dot4(__ldcs(whr + tid), hv);
    float s4 = dot4(__ldcs(whz + tid), hv);
    float s5 = dot4(__ldcs(whn + tid), hv);
    s0 = warp_sum(s0); s1 = warp_sum(s1); s2 = warp_sum(s2);
    s3 = warp_sum(s3); s4 = warp_sum(s4); s5 = warp_sum(s5);
    if (lane == 0) {
        red[0][warp] = s0; red[1][warp] = s1; red[2][warp] = s2;
        red[3][warp] = s3; red[4][warp] = s4; red[5][warp] = s5;
    }
    __syncthreads();
    if (tid == 0) {
        float g[6];
#pragma unroll
        for (int gi = 0; gi < 6; gi++) {
            float acc = 0.f;
#pragma unroll
            for (int w = 0; w < 8; w++) acc += red[gi][w];
            g[gi] = acc;
        }
        float r = 1.f / (1.f + expf(-((g[0] + bih[u]) + (g[3] + bhh[u]))));
        float z = 1.f / (1.f + expf(-((g[1] + bih[Hdim + u]) + (g[4] + bhh[Hdim + u]))));
        float n = tanhf((g[2] + bih[2 * Hdim + u]) + r * (g[5] + bhh[2 * Hdim + u]));
        float hn = (1.f - z) * n + z * hidden[u];
        g_hnew[u] = hn;
        if (out_size >= Vdim + Hdim) out[Vdim + u] = hn;
    }
}

// K5: PERSISTENT logits + FUSED logsumexp + final write.
// Single wave (grid = 2*SMs, launch_bounds(512,2) => all blocks co-resident):
// one software grid barrier replaces the k67 kernel entirely.
__global__ __launch_bounds__(512, 2) void k5_logits(const float* __restrict__ outW,
                                                    const float* __restrict__ outb,
                                                    float* __restrict__ out) {
    __shared__ __align__(16) float sh[Hdim];
    __shared__ float sm[NWARP5], ss[NWARP5];
    __shared__ unsigned s_sense;
    __shared__ float s_shift;
    int tid = threadIdx.x, warp = tid >> 5, lane = tid & 31;

    int per = (Vdim + gridDim.x - 1) / gridDim.x;
    int start = blockIdx.x * per;
    int end = start + per; if (end > Vdim) end = Vdim;

    if (tid == 0) s_sense = g_bar_sense;   // read before any arrival (all blocks)

    {   // warm L2 with this warp's first two rows while predecessors run
        int r0 = start + 2 * warp;
        if (r0 < end) {
            l2_prefetch((const char*)(outW + (size_t)r0 * Hdim) + lane * 128);
            if (r0 + 1 < end)
                l2_prefetch((const char*)(outW + (size_t)(r0 + 1) * Hdim) + lane * 128);
        }
    }
    cudaTriggerProgrammaticLaunchCompletion();
    cudaGridDependencySynchronize();

    sh[tid] = g_hnew[tid];
    sh[tid + 512] = g_hnew[tid + 512];
    __syncthreads();
    const float4* hh = (const float4*)sh;

    float m = -INFINITY, ssum = 0.f;
    for (int r = start + 2 * warp; r < end; r += 2 * NWARP5) {
        int r1 = r + 1;
        bool v1 = r1 < end;
        const float4* w0 = (const float4*)(outW + (size_t)r * Hdim);
        const float4* w1 = (const float4*)(outW + (size_t)(v1 ? r1 : r) * Hdim);
        float a0 = 0.f, a1 = 0.f;
#pragma unroll
        for (int k = 0; k < 8; k++) {
            int idx = lane + 32 * k;
            float4 h = hh[idx];
            a0 += dot4(__ldcs(w0 + idx), h);
            a1 += dot4(__ldcs(w1 + idx), h);
        }
        a0 = warp_sum(a0);
        a1 = warp_sum(a1);
        if (lane == 0) {
            float lg0 = a0 + outb[r];
            g_logits[r] = lg0;
            lse_merge(m, ssum, lg0, 1.f);
            if (v1) {
                float lg1 = a1 + outb[r1];
                g_logits[r1] = lg1;
                lse_merge(m, ssum, lg1, 1.f);
            }
        }
    }
    if (lane == 0) { sm[warp] = m; ss[warp] = ssum; }
    __syncthreads();
    if (tid == 0) {
        float gm = -INFINITY, gs = 0.f;
#pragma unroll
        for (int w = 0; w < NWARP5; w++) lse_merge(gm, gs, sm[w], ss[w]);
        g_pmax[blockIdx.x] = gm;
        g_psum[blockIdx.x] = gs;
    }

    // ---- software grid barrier (all blocks co-resident: single wave) ----
    __syncthreads();
    if (tid == 0) {
        unsigned ns = s_sense ^ 1u;
        __threadfence();
        if (atomicAdd(&g_bar_count, 1u) == gridDim.x - 1) {
            g_bar_count = 0;
            __threadfence();
            g_bar_sense = ns;
        } else {
            while (g_bar_sense != ns) { }
        }
        __threadfence();
    }
    __syncthreads();

    // ---- fused global logsumexp (redundant per block, partials L2-hot) ----
    if (warp == 0) {
        float gm = -INFINITY, gs = 0.f;
        for (int b = lane; b < (int)gridDim.x; b += 32)
            lse_merge(gm, gs, g_pmax[b], g_psum[b]);
#pragma unroll
        for (int off = 16; off; off >>= 1) {
            float m2 = __shfl_xor_sync(0xffffffffu, gm, off);
            float s2 = __shfl_xor_sync(0xffffffffu, gs, off);
            lse_merge(gm, gs, m2, s2);
        }
        if (lane == 0) s_shift = gm + logf(gs);
    }
    __syncthreads();

    // ---- write this block's chunk (logits are L2-hot from our own stores) ----
    for (int v = start + tid; v < end; v += 512)
        out[v] = g_logits[v] - s_shift;
}

static inline void launch_pdl(void* func, dim3 grid, dim3 block, void** args) {
    cudaLaunchAttribute attr[1];
    attr[0].id = cudaLaunchAttributeProgrammaticStreamSerialization;
    attr[0].val.programmaticStreamSerializationAllowed = 1;
    cudaLaunchConfig_t cfg = {};
    cfg.gridDim = grid;
    cfg.blockDim = block;
    cfg.dynamicSmemBytes = 0;
    cfg.stream = 0;
    cfg.attrs = attr;
    cfg.numAttrs = 1;
    cudaLaunchKernelExC(&cfg, func, args);
}

extern "C" void kernel_launch(void* const* d_in, const int* in_sizes, int n_in,
                              void* d_out, int out_size) {
    const int*   inp    = (const int*)  d_in[0];
    const float* hidden = (const float*)d_in[1];
    const float* enc    = (const float*)d_in[2];
    const float* emb    = (const float*)d_in[3];
    const float* attn_W = (const float*)d_in[4];
    const float* attn_b = (const float*)d_in[5];
    const float* comb_W = (const float*)d_in[6];
    const float* comb_b = (const float*)d_in[7];
    const float* gruwih = (const float*)d_in[8];
    const float* gruwhh = (const float*)d_in[9];
    const float* grubih = (const float*)d_in[10];
    const float* grubhh = (const float*)d_in[11];
    const float* out_W  = (const float*)d_in[12];
    const float* out_b  = (const float*)d_in[13];
    float* out = (float*)d_out;

    int dev = 0, nsm = 148;
    cudaGetDevice(&dev);
    cudaDeviceGetAttribute(&nsm, cudaDevAttrMultiProcessorCount, dev);
    int nb5 = 2 * nsm;                       // single wave, all co-resident
    if (nb5 > MAXNB5) nb5 = MAXNB5;
    int nb2 = (Hdim + ROWS2 - 1) / ROWS2;    // 147

    {
        void* args[] = { (void*)&comb_W, (void*)&comb_b, (void*)&inp,
                         (void*)&emb, (void*)&enc, (void*)&attn_W, (void*)&attn_b,
                         (void*)&hidden, (void*)&out, (void*)&out_size };
        launch_pdl((void*)k2_comb, dim3(nb2), dim3(512), args);
    }
    {
        void* args[] = { (void*)&hidden, (void*)&gruwih, (void*)&gruwhh,
                         (void*)&grubih, (void*)&grubhh, (void*)&out, (void*)&out_size };
        launch_pdl((void*)k3_gru, dim3(Hdim), dim3(256), args);
    }
    {
        void* args[] = { (void*)&out_W, (void*)&out_b, (void*)&out };
        launch_pdl((void*)k5_logits, dim3(nb5), dim3(512), args);
    }
}

// round 17
// speedup vs baseline: 1.0915x; 1.0915x over previous
#include <cuda_runtime.h>
#include <cuda_bf16.h>
#include <math.h>

#define Hdim 1024
#define Ldim 10
#define Vdim 50257
#define NWARP5 16
#define MAXNB5 512
#define NB7 ((Vdim + 255) / 256)
#define ROWS2 4      // k2: rows per block (256*4 = 1024)

// ---- scratch (no allocations allowed) ----
__device__ __align__(16) float g_x[Hdim];
__device__ __align__(16) float g_hnew[Hdim];
__device__ __align__(16) float g_logits[Vdim];
__device__ float g_pmax[MAXNB5];
__device__ float g_psum[MAXNB5];

__device__ __forceinline__ float warp_sum(float s) {
#pragma unroll
    for (int o = 16; o; o >>= 1) s += __shfl_down_sync(0xffffffffu, s, o);
    return s;
}

__device__ __forceinline__ void lse_merge(float& m, float& s, float m2, float s2) {
    if (m2 > m) { s = s * expf(m - m2) + s2; m = m2; }
    else if (s2 > 0.f) { s += s2 * expf(m2 - m); }
}

__device__ __forceinline__ void l2_prefetch(const void* p) {
    asm volatile("prefetch.global.L2 [%0];" :: "l"(p));
}

__device__ __forceinline__ float dot4(float4 a, float4 b) {
    return a.x * b.x + a.y * b.y + a.z * b.z + a.w * b.w;
}

// K2: 256 blocks x 512, 4 rows/block, 4 warps per row (all 16 warps active).
// NO gridsync — scores computed in-block from inputs only.
__global__ __launch_bounds__(512) void k2_comb(const float* __restrict__ comb_W,
                                               const float* __restrict__ comb_b,
                                               const int* __restrict__ inp,
                                               const float* __restrict__ emb,
                                               const float* __restrict__ enc,
                                               const float* __restrict__ attn_W,
                                               const float* __restrict__ attn_b,
                                               const float* __restrict__ hidden,
                                               float* __restrict__ out, int out_size) {
    cudaTriggerProgrammaticLaunchCompletion();
    __shared__ __align__(16) float s_xcat[2 * Hdim];
    __shared__ float s_sc[Ldim];
    __shared__ float s_part[ROWS2][4];
    int tid = threadIdx.x, warp = tid >> 5, lane = tid & 31;
    int r0 = blockIdx.x * ROWS2;

    // prefetch this block's 4 comb rows (8KB/row = 64 lines = 256 total)
    if (tid < ROWS2 * 64) {
        int r = r0 + tid / 64;
        if (r < Hdim)
            l2_prefetch((const char*)(comb_W + (size_t)r * 2 * Hdim) + (tid % 64) * 128);
    }
    int tok = inp[0];
    const float4* erow4 = (const float4*)(emb + (size_t)tok * Hdim);
    const float4* h4 = (const float4*)hidden;

    // emb half of xcat straight to smem
    if (tid < 256)
        ((float4*)s_xcat)[tid] = erow4[tid];

    // attention scores (inputs only): warp l computes score l
    if (warp < Ldim) {
        const float4* wr = (const float4*)(attn_W + (size_t)warp * 2 * Hdim);
        float s = 0.f;
#pragma unroll
        for (int k = 0; k < 16; k++) {
            int idx = lane + 32 * k;
            float4 x = (idx < 256) ? erow4[idx] : h4[idx - 256];
            s += dot4(__ldg(wr + idx), x);
        }
        s = warp_sum(s);
        if (lane == 0) s_sc[warp] = s + attn_b[warp];
    }
    __syncthreads();

    // softmax over 10 scores (register-resident, redundant per thread)
    float wl[Ldim];
    {
        float m = s_sc[0];
#pragma unroll
        for (int l = 1; l < Ldim; l++) m = fmaxf(m, s_sc[l]);
        float ssum = 0.f;
#pragma unroll
        for (int l = 0; l < Ldim; l++) { wl[l] = expf(s_sc[l] - m); ssum += wl[l]; }
        float inv = 1.f / ssum;
#pragma unroll
        for (int l = 0; l < Ldim; l++) wl[l] *= inv;
    }
    if (blockIdx.x == 0 && tid < Ldim && out_size >= Vdim + Hdim + Ldim)
        out[Vdim + Hdim + tid] = wl[tid];

    // attn half of xcat
    if (tid < 256) {
        const float4* e4 = (const float4*)enc;
        float4 a = make_float4(0.f, 0.f, 0.f, 0.f);
#pragma unroll
        for (int l = 0; l < Ldim; l++) {
            float4 e = __ldg(e4 + l * 256 + tid);
            a.x += wl[l] * e.x; a.y += wl[l] * e.y;
            a.z += wl[l] * e.z; a.w += wl[l] * e.w;
        }
        ((float4*)s_xcat)[256 + tid] = a;
    }
    __syncthreads();

    // 4 rows x 4 warps: each warp dots a 512-element quarter (4 float4/lane)
    {
        int row = warp >> 2;          // 0..3
        int quarter = warp & 3;       // 0..3
        int r = r0 + row;
        float s = 0.f;
        if (r < Hdim) {
            const float4* wr = (const float4*)(comb_W + (size_t)r * 2 * Hdim);
            const float4* xc = (const float4*)s_xcat;
            int base = quarter * 128;   // float4 index: 128 f4 per quarter
#pragma unroll
            for (int k = 0; k < 4; k++) {
                int idx = base + lane + 32 * k;
                s += dot4(__ldcs(wr + idx), xc[idx]);
            }
        }
        s = warp_sum(s);
        if (lane == 0) s_part[row][quarter] = s;
    }
    __syncthreads();
    if (tid < ROWS2) {
        int r = r0 + tid;
        if (r < Hdim) {
            float v = s_part[tid][0] + s_part[tid][1] + s_part[tid][2] + s_part[tid][3];
            g_x[r] = fmaxf(v + comb_b[r], 0.f);
        }
    }
}

// K3: 1024 blocks x 256 threads, ONE unit each. Pre-sync L2-prefetch of 6 rows.
__global__ __launch_bounds__(256) void k3_gru(const float* __restrict__ hidden,
                                              const float* __restrict__ wih,
                                              const float* __restrict__ whh,
                                              const float* __restrict__ bih,
                                              const float* __restrict__ bhh,
                                              float* __restrict__ out, int out_size) {
    __shared__ float red[6][8];
    int u = blockIdx.x;
    int tid = threadIdx.x, warp = tid >> 5, lane = tid & 31;

    const float4* wir = (const float4*)(wih + (size_t)u * Hdim);
    const float4* wiz = (const float4*)(wih + (size_t)(u + Hdim) * Hdim);
    const float4* win = (const float4*)(wih + (size_t)(u + 2 * Hdim) * Hdim);
    const float4* whr = (const float4*)(whh + (size_t)u * Hdim);
    const float4* whz = (const float4*)(whh + (size_t)(u + Hdim) * Hdim);
    const float4* whn = (const float4*)(whh + (size_t)(u + 2 * Hdim) * Hdim);

    for (int i = tid; i < 192; i += 256) {
        int row6 = i / 32, line = i % 32;
        const float* base;
        if (row6 < 3) base = wih + (size_t)(u + row6 * Hdim) * Hdim;
        else          base = whh + (size_t)(u + (row6 - 3) * Hdim) * Hdim;
        l2_prefetch((const char*)base + line * 128);
    }
    float4 hv = ((const float4*)hidden)[tid];

    cudaTriggerProgrammaticLaunchCompletion();
    cudaGridDependencySynchronize();

    float4 xv = ((const float4*)g_x)[tid];
    float s0 = dot4(__ldcs(wir + tid), xv);
    float s1 = dot4(__ldcs(wiz + tid), xv);
    float s2 = dot4(__ldcs(win + tid), xv);
    float s3 = dot4(__ldcs(whr + tid), hv);
    float s4 = dot4(__ldcs(whz + tid), hv);
    float s5 = dot4(__ldcs(whn + tid), hv);
    s0 = warp_sum(s0); s1 = warp_sum(s1); s2 = warp_sum(s2);
    s3 = warp_sum(s3); s4 = warp_sum(s4); s5 = warp_sum(s5);
    if (lane == 0) {
        red[0][warp] = s0; red[1][warp] = s1; red[2][warp] = s2;
        red[3][warp] = s3; red[4][warp] = s4; red[5][warp] = s5;
    }
    __syncthreads();
    if (tid == 0) {
        float g[6];
#pragma unroll
        for (int gi = 0; gi < 6; gi++) {
            float acc = 0.f;
#pragma unroll
            for (int w = 0; w < 8; w++) acc += red[gi][w];
            g[gi] = acc;
        }
        float r = 1.f / (1.f + expf(-((g[0] + bih[u]) + (g[3] + bhh[u]))));
        float z = 1.f / (1.f + expf(-((g[1] + bih[Hdim + u]) + (g[4] + bhh[Hdim + u]))));
        float n = tanhf((g[2] + bih[2 * Hdim + u]) + r * (g[5] + bhh[2 * Hdim + u]));
        float hn = (1.f - z) * n + z * hidden[u];
        g_hnew[u] = hn;
        if (out_size >= Vdim + Hdim) out[Vdim + u] = hn;
    }
}

// K5: PERSISTENT logits + per-block (max,sumexp). One wave: grid = 2*SMs.
__global__ __launch_bounds__(512, 2) void k5_logits(const float* __restrict__ outW,
                                                    const float* __restrict__ outb) {
    __shared__ __align__(16) float sh[Hdim];
    __shared__ float sm[NWARP5], ss[NWARP5];
    int tid = threadIdx.x, warp = tid >> 5, lane = tid & 31;

    int per = (Vdim + gridDim.x - 1) / gridDim.x;
    int start = blockIdx.x * per;
    int end = start + per; if (end > Vdim) end = Vdim;

    {   // warm L2 with this warp's first two rows while predecessors run
        int r0 = start + 2 * warp;
        if (r0 < end) {
            l2_prefetch((const char*)(outW + (size_t)r0 * Hdim) + lane * 128);
            if (r0 + 1 < end)
                l2_prefetch((const char*)(outW + (size_t)(r0 + 1) * Hdim) + lane * 128);
        }
    }
    cudaTriggerProgrammaticLaunchCompletion();
    cudaGridDependencySynchronize();

    sh[tid] = g_hnew[tid];
    sh[tid + 512] = g_hnew[tid + 512];
    __syncthreads();
    const float4* hh = (const float4*)sh;

    float m = -INFINITY, ssum = 0.f;
    for (int r = start + 2 * warp; r < end; r += 2 * NWARP5) {
        int r1 = r + 1;
        bool v1 = r1 < end;
        const float4* w0 = (const float4*)(outW + (size_t)r * Hdim);
        const float4* w1 = (const float4*)(outW + (size_t)(v1 ? r1 : r) * Hdim);
        float a0 = 0.f, a1 = 0.f;
#pragma unroll
        for (int k = 0; k < 8; k++) {
            int idx = lane + 32 * k;
            float4 h = hh[idx];
            a0 += dot4(__ldcs(w0 + idx), h);
            a1 += dot4(__ldcs(w1 + idx), h);
        }
        a0 = warp_sum(a0);
        a1 = warp_sum(a1);
        if (lane == 0) {
            float lg0 = a0 + outb[r];
            g_logits[r] = lg0;
            lse_merge(m, ssum, lg0, 1.f);
            if (v1) {
                float lg1 = a1 + outb[r1];
                g_logits[r1] = lg1;
                lse_merge(m, ssum, lg1, 1.f);
            }
        }
    }
    if (lane == 0) { sm[warp] = m; ss[warp] = ssum; }
    __syncthreads();
    if (tid == 0) {
        float gm = -INFINITY, gs = 0.f;
#pragma unroll
        for (int w = 0; w < NWARP5; w++) lse_merge(gm, gs, sm[w], ss[w]);
        g_pmax[blockIdx.x] = gm;
        g_psum[blockIdx.x] = gs;
    }
}

// K67: global logsumexp reduce (redundant per block) + output write.
__global__ __launch_bounds__(256) void k67_write(float* __restrict__ out, int nb5) {
    cudaGridDependencySynchronize();
    __shared__ float sm[256], ss[256];
    int tid = threadIdx.x;
    float m = -INFINITY, s = 0.f;
    for (int b = tid; b < nb5; b += 256)
        lse_merge(m, s, g_pmax[b], g_psum[b]);
    sm[tid] = m; ss[tid] = s;
    __syncthreads();
#pragma unroll
    for (int o = 128; o; o >>= 1) {
        if (tid < o) lse_merge(sm[tid], ss[tid], sm[tid + o], ss[tid + o]);
        __syncthreads();
    }
    __shared__ float shift;
    if (tid == 0) shift = sm[0] + logf(ss[0]);
    __syncthreads();
    int v = blockIdx.x * 256 + tid;
    if (v < Vdim) out[v] = g_logits[v] - shift;
}

static inline void launch_pdl(void* func, dim3 grid, dim3 block, void** args) {
    cudaLaunchAttribute attr[1];
    attr[0].id = cudaLaunchAttributeProgrammaticStreamSerialization;
    attr[0].val.programmaticStreamSerializationAllowed = 1;
    cudaLaunchConfig_t cfg = {};
    cfg.gridDim = grid;
    cfg.blockDim = block;
    cfg.dynamicSmemBytes = 0;
    cfg.stream = 0;
    cfg.attrs = attr;
    cfg.numAttrs = 1;
    cudaLaunchKernelExC(&cfg, func, args);
}

extern "C" void kernel_launch(void* const* d_in, const int* in_sizes, int n_in,
                              void* d_out, int out_size) {
    const int*   inp    = (const int*)  d_in[0];
    const float* hidden = (const float*)d_in[1];
    const float* enc    = (const float*)d_in[2];
    const float* emb    = (const float*)d_in[3];
    const float* attn_W = (const float*)d_in[4];
    const float* attn_b = (const float*)d_in[5];
    const float* comb_W = (const float*)d_in[6];
    const float* comb_b = (const float*)d_in[7];
    const float* gruwih = (const float*)d_in[8];
    const float* gruwhh = (const float*)d_in[9];
    const float* grubih = (const float*)d_in[10];
    const float* grubhh = (const float*)d_in[11];
    const float* out_W  = (const float*)d_in[12];
    const float* out_b  = (const float*)d_in[13];
    float* out = (float*)d_out;

    int dev = 0, nsm = 148;
    cudaGetDevice(&dev);
    cudaDeviceGetAttribute(&nsm, cudaDevAttrMultiProcessorCount, dev);
    int nb5 = 2 * nsm;
    if (nb5 > MAXNB5) nb5 = MAXNB5;
    int nb2 = Hdim / ROWS2;                  // 256

    {
        void* args[] = { (void*)&comb_W, (void*)&comb_b, (void*)&inp,
                         (void*)&emb, (void*)&enc, (void*)&attn_W, (void*)&attn_b,
                         (void*)&hidden, (void*)&out, (void*)&out_size };
        launch_pdl((void*)k2_comb, dim3(nb2), dim3(512), args);
    }
    {
        void* args[] = { (void*)&hidden, (void*)&gruwih, (void*)&gruwhh,
                         (void*)&grubih, (void*)&grubhh, (void*)&out, (void*)&out_size };
        launch_pdl((void*)k3_gru, dim3(Hdim), dim3(256), args);
    }
    {
        void* args[] = { (void*)&out_W, (void*)&out_b };
        launch_pdl((void*)k5_logits, dim3(nb5), dim3(512), args);
    }
    {
        void* args[] = { (void*)&out, (void*)&nb5 };
        launch_pdl((void*)k67_write, dim3(NB7), dim3(256), args);
    }
}